// round 1
// baseline (speedup 1.0000x reference)
#include <cuda_runtime.h>
#include <math.h>

#define BB 32
#define NN 300
#define TT 12
#define DD 64
#define MM 16
#define BT (BB*TT)        // 384
#define ND (NN*DD)        // 19200
#define NN2 (NN*NN)       // 90000

// ---- scratch (device globals; no runtime allocation) ----
__device__ float g_S[NN2];             // alpha1@alpha2
__device__ float g_Bm[NN2];            // beta1@beta2
__device__ float g_W[NN*DD*DD];        // per-node weights [N,64,64]
__device__ float g_gcnWT4[192*DD];     // gcnW rearranged [(f/4)*64+d]*4+i
__device__ float g_A[(size_t)BT*NN2];  // adjacency per (b,t)   ~138MB
__device__ float g_Xp[(size_t)BT*ND];  // X transposed [bt][n][d]
__device__ float g_H1[(size_t)BT*ND];
__device__ float g_H2[(size_t)BT*ND];
__device__ float g_Tmp[(size_t)BT*ND];

// ---------------- tiny precompute kernels ----------------
__global__ void k_SB(const float* __restrict__ a1, const float* __restrict__ a2,
                     const float* __restrict__ b1, const float* __restrict__ b2) {
    int idx = blockIdx.x*256 + threadIdx.x;
    if (idx >= NN2) return;
    int i = idx / NN, k = idx % NN;
    float s = 0.f, bm = 0.f;
#pragma unroll
    for (int m = 0; m < MM; m++) {
        s  += a1[i*MM+m] * a2[m*NN+k];
        bm += b1[i*MM+m] * b2[m*NN+k];
    }
    g_S[idx] = s; g_Bm[idx] = bm;
}

__global__ void k_Wp(const float* __restrict__ w1, const float* __restrict__ w2) {
    int idx = blockIdx.x*256 + threadIdx.x;
    if (idx >= NN*DD*DD) return;
    int n = idx / (DD*DD), r = idx % (DD*DD);
    float s = 0.f;
#pragma unroll
    for (int m = 0; m < MM; m++) s += w1[n*MM+m] * w2[m*DD*DD+r];
    g_W[idx] = s;
}

__global__ void k_gWT(const float* __restrict__ gcnW) {
    int idx = blockIdx.x*256 + threadIdx.x;
    if (idx >= 192*DD) return;
    int i  = idx & 3;
    int d  = (idx >> 2) & 63;
    int f4 = idx >> 8;
    g_gcnWT4[idx] = gcnW[d*192 + f4*4 + i];
}

// transpose X[b,d,n,t] -> Xp[bt][n][d]
__global__ void k_txp(const float* __restrict__ X) {
    int n = blockIdx.x, b = blockIdx.y;
    __shared__ float tile[DD][13];
    int tid = threadIdx.x;
#pragma unroll
    for (int i = 0; i < 3; i++) {
        int lin = tid + i*256;
        if (lin < DD*TT) {
            int d = lin / TT, t = lin % TT;
            tile[d][t] = X[(((size_t)b*DD+d)*NN+n)*TT + t];
        }
    }
    __syncthreads();
#pragma unroll
    for (int i = 0; i < 3; i++) {
        int lin = tid + i*256;
        if (lin < DD*TT) {
            int t = lin >> 6, d = lin & 63;
            g_Xp[(size_t)(b*TT+t)*ND + n*DD + d] = tile[d][t];
        }
    }
}

// ---------------- adjacency: A = relu(S * sin(te@adjW^T + adjB) + Bm) ----------------
// tile: 128 rows(n) x 64 cols(k), K = D = 64 in 2 chunks of 32
__global__ void __launch_bounds__(256) k_adj(const float* __restrict__ te,
                                             const float* __restrict__ adjW,
                                             const float* __restrict__ adjB) {
    const int bt = blockIdx.y;
    const int b = bt / TT, t = bt % TT;
    const int rt = blockIdx.x % 3;     // 3 row tiles cover 300
    const int ct = blockIdx.x / 3;     // 5 col tiles
    const int rowBase = rt*128, colBase = ct*64;
    __shared__ __align__(16) float As[128][33];
    __shared__ __align__(16) float Bs[32][68];
    const int tid = threadIdx.x;
    const int tx = tid & 15, ty = tid >> 4;
    float acc[8][4] = {};

    for (int k0 = 0; k0 < DD; k0 += 32) {
#pragma unroll
        for (int i = 0; i < 16; i++) {
            int lin = tid + i*256;
            int r = lin >> 5, kk = lin & 31;
            int row = rowBase + r;
            As[r][kk] = (row < NN) ? te[(((size_t)b*NN + row)*TT + t)*DD + k0 + kk] : 0.f;
        }
#pragma unroll
        for (int i = 0; i < 8; i++) {
            int lin = tid + i*256;
            int kk = lin & 31, c = lin >> 5;
            int col = colBase + c;
            Bs[kk][c] = (col < NN) ? adjW[col*DD + k0 + kk] : 0.f;
        }
        __syncthreads();
#pragma unroll
        for (int kk = 0; kk < 32; kk++) {
            float4 b4 = *(const float4*)&Bs[kk][tx*4];
#pragma unroll
            for (int ii = 0; ii < 8; ii++) {
                float a = As[ty*8+ii][kk];
                acc[ii][0] += a*b4.x; acc[ii][1] += a*b4.y;
                acc[ii][2] += a*b4.z; acc[ii][3] += a*b4.w;
            }
        }
        __syncthreads();
    }

    float* Aout = g_A + (size_t)bt*NN2;
#pragma unroll
    for (int ii = 0; ii < 8; ii++) {
        int row = rowBase + ty*8 + ii;
        if (row >= NN) continue;
#pragma unroll
        for (int jj = 0; jj < 4; jj++) {
            int col = colBase + tx*4 + jj;
            if (col >= NN) continue;
            float v = sinf(acc[ii][jj] + adjB[col]);
            v = g_S[row*NN+col]*v + g_Bm[row*NN+col];
            Aout[(size_t)row*NN + col] = v > 0.f ? v : 0.f;
        }
    }
}

// ---------------- Tmp = A @ Hb  (per bt: [300,300]@[300,64]) ----------------
__global__ void __launch_bounds__(256) k_mm(int hop) {
    const int bt = blockIdx.y;
    const int rowBase = blockIdx.x*128;
    const float* Hb = (hop == 0) ? g_Xp : g_H1;
    const float* Abt = g_A + (size_t)bt*NN2;
    const float* Hbt = Hb + (size_t)bt*ND;
    __shared__ __align__(16) float As[128][33];
    __shared__ __align__(16) float Bs[32][68];
    const int tid = threadIdx.x;
    const int tx = tid & 15, ty = tid >> 4;
    float acc[8][4] = {};

    for (int k0 = 0; k0 < 320; k0 += 32) {
#pragma unroll
        for (int i = 0; i < 16; i++) {
            int lin = tid + i*256;
            int r = lin >> 5, kk = lin & 31;
            int row = rowBase + r, k = k0 + kk;
            As[r][kk] = (row < NN && k < NN) ? Abt[(size_t)row*NN + k] : 0.f;
        }
#pragma unroll
        for (int i = 0; i < 8; i++) {
            int lin = tid + i*256;
            int d = lin & 63, kk = lin >> 6;
            int k = k0 + kk;
            Bs[kk][d] = (k < NN) ? Hbt[k*DD + d] : 0.f;
        }
        __syncthreads();
#pragma unroll
        for (int kk = 0; kk < 32; kk++) {
            float4 b4 = *(const float4*)&Bs[kk][tx*4];
#pragma unroll
            for (int ii = 0; ii < 8; ii++) {
                float a = As[ty*8+ii][kk];
                acc[ii][0] += a*b4.x; acc[ii][1] += a*b4.y;
                acc[ii][2] += a*b4.z; acc[ii][3] += a*b4.w;
            }
        }
        __syncthreads();
    }

    float* Tbt = g_Tmp + (size_t)bt*ND;
#pragma unroll
    for (int ii = 0; ii < 8; ii++) {
        int row = rowBase + ty*8 + ii;
        if (row >= NN) continue;
        *(float4*)&Tbt[row*DD + tx*4] =
            make_float4(acc[ii][0], acc[ii][1], acc[ii][2], acc[ii][3]);
    }
}

// ---------------- per-node matmul + gated residual ----------------
// H[bt,n,:] = g(Xp[bt,n,:] + Tmp[bt,n,:] @ W[n]),  g(x)=sigmoid(x)*tanh(x)
// block: node n fixed, 32 bt-rows x 64 cols; W[n] resident in smem
__global__ void __launch_bounds__(256) k_nodemm(int hop) {
    const int n = blockIdx.y;
    const int btBase = blockIdx.x*32;
    float* Hout = (hop == 0) ? g_H1 : g_H2;
    __shared__ __align__(16) float Ws[DD*DD];   // 16KB
    __shared__ __align__(16) float Ts[32*DD];   // 8KB
    const int tid = threadIdx.x;
    const int d = tid & 63, ty = tid >> 6;
    const float* Wn = g_W + (size_t)n*DD*DD;
#pragma unroll
    for (int i = 0; i < 16; i++) Ws[tid + i*256] = Wn[tid + i*256];
#pragma unroll
    for (int i = 0; i < 8; i++) {
        int lin = tid + i*256;
        int r = lin >> 6, dd = lin & 63;
        Ts[lin] = g_Tmp[(size_t)(btBase + r)*ND + n*DD + dd];
    }
    __syncthreads();
    float acc[8] = {};
#pragma unroll
    for (int k = 0; k < DD; k += 4) {
        float w0 = Ws[k*DD+d], w1 = Ws[(k+1)*DD+d];
        float w2 = Ws[(k+2)*DD+d], w3 = Ws[(k+3)*DD+d];
#pragma unroll
        for (int j = 0; j < 8; j++) {
            float4 t4 = *(const float4*)&Ts[(ty*8+j)*DD + k];
            acc[j] += t4.x*w0 + t4.y*w1 + t4.z*w2 + t4.w*w3;
        }
    }
#pragma unroll
    for (int j = 0; j < 8; j++) {
        size_t idx = (size_t)(btBase + ty*8 + j)*ND + n*DD + d;
        float pre = g_Xp[idx] + acc[j];
        float sg = 1.f / (1.f + expf(-pre));
        Hout[idx] = sg * tanhf(pre);
    }
}

// ---------------- output: Hout = [Xp|H1|H2] @ gcnW^T + gcnB, write [B,D,N,T] ----------------
__global__ void __launch_bounds__(256) k_out(const float* __restrict__ gcnB,
                                             float* __restrict__ out) {
    const int b = blockIdx.y;
    const int nBase = blockIdx.x*4;
    __shared__ __align__(16) float Hc[4*12*192];   // 36.9KB
    const int tid = threadIdx.x;
#pragma unroll
    for (int i = 0; i < 36; i++) {
        int lin = tid + i*256;
        int nloc = lin / 2304;
        int r = lin - nloc*2304;
        int t = r / 192;
        int f = r - t*192;
        int seg = f >> 6, fd = f & 63;
        const float* src = (seg == 0) ? g_Xp : ((seg == 1) ? g_H1 : g_H2);
        Hc[lin] = src[(size_t)(b*TT+t)*ND + (nBase+nloc)*DD + fd];
    }
    __syncthreads();
    const int d = tid & 63, nloc = tid >> 6;
    float acc[12] = {};
    const float4* WT = (const float4*)g_gcnWT4;
#pragma unroll 4
    for (int f4 = 0; f4 < 48; f4++) {
        float4 w = WT[f4*64 + d];
        const float* hb = &Hc[nloc*2304 + f4*4];
#pragma unroll
        for (int t = 0; t < 12; t++) {
            float4 h = *(const float4*)&hb[t*192];
            acc[t] += h.x*w.x + h.y*w.y + h.z*w.z + h.w*w.w;
        }
    }
    const float bias = gcnB[d];
    const int n = nBase + nloc;
    float* op = out + ((size_t)(b*DD+d)*NN + n)*TT;
#pragma unroll
    for (int t = 0; t < 12; t++) op[t] = acc[t] + bias;
}

// ---------------- launcher ----------------
extern "C" void kernel_launch(void* const* d_in, const int* in_sizes, int n_in,
                              void* d_out, int out_size) {
    const float* X    = (const float*)d_in[0];
    const float* te   = (const float*)d_in[1];
    const float* adjW = (const float*)d_in[2];
    const float* adjB = (const float*)d_in[3];
    const float* tW1  = (const float*)d_in[4];
    const float* tW2  = (const float*)d_in[5];
    const float* a1   = (const float*)d_in[6];
    const float* a2   = (const float*)d_in[7];
    const float* b1   = (const float*)d_in[8];
    const float* b2   = (const float*)d_in[9];
    const float* gcnW = (const float*)d_in[10];
    const float* gcnB = (const float*)d_in[11];
    float* out = (float*)d_out;

    k_SB <<<(NN2 + 255)/256, 256>>>(a1, a2, b1, b2);
    k_Wp <<<(NN*DD*DD + 255)/256, 256>>>(tW1, tW2);
    k_gWT<<<(192*DD + 255)/256, 256>>>(gcnW);
    k_txp<<<dim3(NN, BB), 256>>>(X);

    k_adj<<<dim3(15, BT), 256>>>(te, adjW, adjB);

    // hop 1
    k_mm    <<<dim3(3, BT), 256>>>(0);
    k_nodemm<<<dim3(12, NN), 256>>>(0);
    // hop 2
    k_mm    <<<dim3(3, BT), 256>>>(1);
    k_nodemm<<<dim3(12, NN), 256>>>(1);

    k_out<<<dim3(75, BB), 256>>>(gcnB, out);
}

// round 3
// speedup vs baseline: 1.5827x; 1.5827x over previous
#include <cuda_runtime.h>
#include <math.h>

#define BB 32
#define NN 300
#define TT 12
#define DD 64
#define MM 16
#define BT (BB*TT)        // 384
#define ND (NN*DD)        // 19200
#define NN2 (NN*NN)       // 90000

// ---- scratch (device globals; no runtime allocation) ----
__device__ float g_S[NN2];             // alpha1@alpha2
__device__ float g_Bm[NN2];            // beta1@beta2
__device__ float g_W[NN*DD*DD];        // per-node weights [N,64,64]
__device__ float g_gcnWT4[192*DD];     // gcnW rearranged [(f/4)*64+d]*4+i
__device__ float g_A[(size_t)BT*NN2];  // adjacency per (b,t)   ~138MB
__device__ float g_Xp[(size_t)BT*ND];  // X transposed [bt][n][d]
__device__ float g_H1[(size_t)BT*ND];
__device__ float g_H2[(size_t)BT*ND];
__device__ float g_Tmp[(size_t)BT*ND];

// ---- packed fp32x2 helpers (SASS FFMA2 path) ----
typedef unsigned long long u64;

__device__ __forceinline__ void fma2(u64 &d, u64 a, u64 b) {
    asm("fma.rn.f32x2 %0, %1, %2, %3;" : "=l"(d) : "l"(a), "l"(b), "l"(d));
}
__device__ __forceinline__ u64 rep2(float x) {
    u64 r; unsigned int u = __float_as_uint(x);
    asm("mov.b64 %0, {%1,%1};" : "=l"(r) : "r"(u));
    return r;
}
__device__ __forceinline__ float lo2(u64 v) { return __uint_as_float((unsigned)v); }
__device__ __forceinline__ float hi2(u64 v) { return __uint_as_float((unsigned)(v >> 32)); }

// ---------------- tiny precompute kernels ----------------
__global__ void k_SB(const float* __restrict__ a1, const float* __restrict__ a2,
                     const float* __restrict__ b1, const float* __restrict__ b2) {
    int idx = blockIdx.x*256 + threadIdx.x;
    if (idx >= NN2) return;
    int i = idx / NN, k = idx % NN;
    float s = 0.f, bm = 0.f;
#pragma unroll
    for (int m = 0; m < MM; m++) {
        s  += a1[i*MM+m] * a2[m*NN+k];
        bm += b1[i*MM+m] * b2[m*NN+k];
    }
    g_S[idx] = s; g_Bm[idx] = bm;
}

__global__ void k_Wp(const float* __restrict__ w1, const float* __restrict__ w2) {
    int idx = blockIdx.x*256 + threadIdx.x;
    if (idx >= NN*DD*DD) return;
    int n = idx / (DD*DD), r = idx % (DD*DD);
    float s = 0.f;
#pragma unroll
    for (int m = 0; m < MM; m++) s += w1[n*MM+m] * w2[m*DD*DD+r];
    g_W[idx] = s;
}

__global__ void k_gWT(const float* __restrict__ gcnW) {
    int idx = blockIdx.x*256 + threadIdx.x;
    if (idx >= 192*DD) return;
    int i  = idx & 3;
    int d  = (idx >> 2) & 63;
    int f4 = idx >> 8;
    g_gcnWT4[idx] = gcnW[d*192 + f4*4 + i];
}

// transpose X[b,d,n,t] -> Xp[bt][n][d]
__global__ void k_txp(const float* __restrict__ X) {
    int n = blockIdx.x, b = blockIdx.y;
    __shared__ float tile[DD][13];
    int tid = threadIdx.x;
#pragma unroll
    for (int i = 0; i < 3; i++) {
        int lin = tid + i*256;
        if (lin < DD*TT) {
            int d = lin / TT, t = lin % TT;
            tile[d][t] = X[(((size_t)b*DD+d)*NN+n)*TT + t];
        }
    }
    __syncthreads();
#pragma unroll
    for (int i = 0; i < 3; i++) {
        int lin = tid + i*256;
        if (lin < DD*TT) {
            int t = lin >> 6, d = lin & 63;
            g_Xp[(size_t)(b*TT+t)*ND + n*DD + d] = tile[d][t];
        }
    }
}

// ---------------- adjacency: A = relu(S * sin(te@adjW^T + adjB) + Bm) ----------------
// tile 128 rows x 64 cols, 128 threads, 8x8 micro-tile via FFMA2
__global__ void __launch_bounds__(128) k_adj(const float* __restrict__ te,
                                             const float* __restrict__ adjW,
                                             const float* __restrict__ adjB) {
    const int bt = blockIdx.y;
    const int b = bt / TT, t = bt % TT;
    const int rt = blockIdx.x % 3;     // 3 row tiles
    const int ct = blockIdx.x / 3;     // 5 col tiles (covers 320, masked at 300)
    const int rowBase = rt*128, colBase = ct*64;
    __shared__ __align__(16) float As_t[32][132];   // [kk][row]
    __shared__ __align__(16) float Bs[32][68];      // [kk][col]
    const int tid = threadIdx.x;
    const int tx = tid & 7;       // 8 col groups
    const int ty = tid >> 3;      // 16 row groups
    u64 acc[4][8] = {};

    for (int k0 = 0; k0 < DD; k0 += 32) {
        // A: thread tid = local row; 8 float4 along k, scatter transposed
        {
            int row = rowBase + tid;
            const float* src = te + (((size_t)b*NN + row)*TT + t)*DD + k0;
#pragma unroll
            for (int c = 0; c < 8; c++) {
                float4 v = (row < NN) ? *(const float4*)(src + 4*c)
                                      : make_float4(0.f,0.f,0.f,0.f);
                As_t[4*c+0][tid] = v.x; As_t[4*c+1][tid] = v.y;
                As_t[4*c+2][tid] = v.z; As_t[4*c+3][tid] = v.w;
            }
        }
        // B: adjW[col][k] -> Bs[kk][col]
#pragma unroll
        for (int i = 0; i < 4; i++) {
            int lin = tid + i*128;                  // 0..511
            int col = lin >> 3, kc = lin & 7;
            int gcol = colBase + col;
            float4 v = (gcol < NN) ? *(const float4*)(adjW + gcol*DD + k0 + kc*4)
                                   : make_float4(0.f,0.f,0.f,0.f);
            Bs[kc*4+0][col] = v.x; Bs[kc*4+1][col] = v.y;
            Bs[kc*4+2][col] = v.z; Bs[kc*4+3][col] = v.w;
        }
        __syncthreads();
#pragma unroll 8
        for (int kk = 0; kk < 32; kk++) {
            ulonglong2 ap0 = *(const ulonglong2*)&As_t[kk][ty*8];
            ulonglong2 ap1 = *(const ulonglong2*)&As_t[kk][ty*8+4];
            float4 b0 = *(const float4*)&Bs[kk][tx*8];
            float4 b1 = *(const float4*)&Bs[kk][tx*8+4];
            u64 ap[4] = {ap0.x, ap0.y, ap1.x, ap1.y};
            u64 br[8] = {rep2(b0.x),rep2(b0.y),rep2(b0.z),rep2(b0.w),
                         rep2(b1.x),rep2(b1.y),rep2(b1.z),rep2(b1.w)};
#pragma unroll
            for (int i = 0; i < 4; i++)
#pragma unroll
                for (int j = 0; j < 8; j++)
                    fma2(acc[i][j], ap[i], br[j]);
        }
        __syncthreads();
    }

    // epilogue: sin / scale / relu
    float* Aout = g_A + (size_t)bt*NN2;
    const int c0 = colBase + tx*8;
#pragma unroll
    for (int i = 0; i < 4; i++) {
        int r0 = rowBase + ty*8 + 2*i;
#pragma unroll
        for (int lane = 0; lane < 2; lane++) {
            int row = r0 + lane;
            if (row >= NN) continue;
#pragma unroll
            for (int j = 0; j < 8; j++) {
                int col = c0 + j;
                if (col >= NN) continue;
                float pre = lane ? hi2(acc[i][j]) : lo2(acc[i][j]);
                float v = sinf(pre + adjB[col]);
                v = g_S[row*NN+col]*v + g_Bm[row*NN+col];
                Aout[(size_t)row*NN + col] = v > 0.f ? v : 0.f;
            }
        }
    }
}

// ---------------- Tmp = A @ Hb  (per bt: [300,300]@[300,64]) ----------------
__global__ void __launch_bounds__(128) k_mm(int hop) {
    const int bt = blockIdx.y;
    const int rowBase = blockIdx.x*128;
    const float* Hb = (hop == 0) ? g_Xp : g_H1;
    const float* Abt = g_A + (size_t)bt*NN2;
    const float* Hbt = Hb + (size_t)bt*ND;
    __shared__ __align__(16) float As_t[32][132];   // [kk][row]
    __shared__ __align__(16) float Bs[32][68];      // [kk][d]
    const int tid = threadIdx.x;
    const int tx = tid & 7;
    const int ty = tid >> 3;
    u64 acc[4][8] = {};

    for (int k0 = 0; k0 < 320; k0 += 32) {
        // A: thread tid = local row; transpose-stage
        {
            int row = rowBase + tid;
            const float* src = Abt + (size_t)row*NN + k0;
#pragma unroll
            for (int c = 0; c < 8; c++) {
                float4 v;
                if (row < NN && (k0 + 4*c + 3) < NN) v = *(const float4*)(src + 4*c);
                else v = make_float4(0.f,0.f,0.f,0.f);
                As_t[4*c+0][tid] = v.x; As_t[4*c+1][tid] = v.y;
                As_t[4*c+2][tid] = v.z; As_t[4*c+3][tid] = v.w;
            }
        }
        // B: Hbt[k][d] row-major, direct copy
#pragma unroll
        for (int i = 0; i < 4; i++) {
            int lin = tid + i*128;                  // 0..511 float4s
            int kk = lin >> 4, d4 = lin & 15;
            int k = k0 + kk;
            float4 v = (k < NN) ? *(const float4*)(Hbt + (size_t)k*DD + d4*4)
                                : make_float4(0.f,0.f,0.f,0.f);
            *(float4*)&Bs[kk][d4*4] = v;
        }
        __syncthreads();
#pragma unroll 8
        for (int kk = 0; kk < 32; kk++) {
            ulonglong2 ap0 = *(const ulonglong2*)&As_t[kk][ty*8];
            ulonglong2 ap1 = *(const ulonglong2*)&As_t[kk][ty*8+4];
            float4 b0 = *(const float4*)&Bs[kk][tx*8];
            float4 b1 = *(const float4*)&Bs[kk][tx*8+4];
            u64 ap[4] = {ap0.x, ap0.y, ap1.x, ap1.y};
            u64 br[8] = {rep2(b0.x),rep2(b0.y),rep2(b0.z),rep2(b0.w),
                         rep2(b1.x),rep2(b1.y),rep2(b1.z),rep2(b1.w)};
#pragma unroll
            for (int i = 0; i < 4; i++)
#pragma unroll
                for (int j = 0; j < 8; j++)
                    fma2(acc[i][j], ap[i], br[j]);
        }
        __syncthreads();
    }

    float* Tbt = g_Tmp + (size_t)bt*ND;
    const int c0 = tx*8;
#pragma unroll
    for (int i = 0; i < 4; i++) {
        int r0 = rowBase + ty*8 + 2*i;
        if (r0 < NN) {
            *(float4*)&Tbt[(size_t)r0*DD + c0] =
                make_float4(lo2(acc[i][0]), lo2(acc[i][1]), lo2(acc[i][2]), lo2(acc[i][3]));
            *(float4*)&Tbt[(size_t)r0*DD + c0 + 4] =
                make_float4(lo2(acc[i][4]), lo2(acc[i][5]), lo2(acc[i][6]), lo2(acc[i][7]));
        }
        if (r0 + 1 < NN) {
            *(float4*)&Tbt[(size_t)(r0+1)*DD + c0] =
                make_float4(hi2(acc[i][0]), hi2(acc[i][1]), hi2(acc[i][2]), hi2(acc[i][3]));
            *(float4*)&Tbt[(size_t)(r0+1)*DD + c0 + 4] =
                make_float4(hi2(acc[i][4]), hi2(acc[i][5]), hi2(acc[i][6]), hi2(acc[i][7]));
        }
    }
}

// ---------------- per-node matmul + gated residual ----------------
__global__ void __launch_bounds__(256) k_nodemm(int hop) {
    const int n = blockIdx.y;
    const int btBase = blockIdx.x*32;
    float* Hout = (hop == 0) ? g_H1 : g_H2;
    __shared__ __align__(16) float Ws[DD*DD];   // 16KB
    __shared__ __align__(16) float Ts[32*DD];   // 8KB
    const int tid = threadIdx.x;
    const int d = tid & 63, ty = tid >> 6;
    const float* Wn = g_W + (size_t)n*DD*DD;
#pragma unroll
    for (int i = 0; i < 16; i++) Ws[tid + i*256] = Wn[tid + i*256];
#pragma unroll
    for (int i = 0; i < 8; i++) {
        int lin = tid + i*256;
        int r = lin >> 6, dd = lin & 63;
        Ts[lin] = g_Tmp[(size_t)(btBase + r)*ND + n*DD + dd];
    }
    __syncthreads();
    float acc[8] = {};
#pragma unroll
    for (int k = 0; k < DD; k += 4) {
        float w0 = Ws[k*DD+d], w1 = Ws[(k+1)*DD+d];
        float w2 = Ws[(k+2)*DD+d], w3 = Ws[(k+3)*DD+d];
#pragma unroll
        for (int j = 0; j < 8; j++) {
            float4 t4 = *(const float4*)&Ts[(ty*8+j)*DD + k];
            acc[j] += t4.x*w0 + t4.y*w1 + t4.z*w2 + t4.w*w3;
        }
    }
#pragma unroll
    for (int j = 0; j < 8; j++) {
        size_t idx = (size_t)(btBase + ty*8 + j)*ND + n*DD + d;
        float pre = g_Xp[idx] + acc[j];
        float sg = 1.f / (1.f + expf(-pre));
        Hout[idx] = sg * tanhf(pre);
    }
}

// ---------------- output: Hout = [Xp|H1|H2] @ gcnW^T + gcnB, write [B,D,N,T] ----------------
// 128 threads: nloc = tid>>5 (4 nodes), d2 = tid&31 handles d2 and d2+32
__global__ void __launch_bounds__(128) k_out(const float* __restrict__ gcnB,
                                             float* __restrict__ out) {
    const int b = blockIdx.y;
    const int nBase = blockIdx.x*4;
    __shared__ __align__(16) float Hc[4*12*192];   // 36.9KB
    const int tid = threadIdx.x;
    float4* Hc4 = (float4*)Hc;
#pragma unroll
    for (int i = 0; i < 18; i++) {
        int lin4 = tid + i*128;                    // 0..2303 float4s
        int nl = lin4 / 576;
        int rem = lin4 - nl*576;
        int t = rem / 48;
        int f4 = rem - t*48;
        int seg = f4 >> 4, fd4 = f4 & 15;
        const float* src = (seg == 0) ? g_Xp : ((seg == 1) ? g_H1 : g_H2);
        Hc4[lin4] = *(const float4*)(src + (size_t)(b*TT+t)*ND + (nBase+nl)*DD + fd4*4);
    }
    __syncthreads();
    const int d2 = tid & 31, nloc = tid >> 5;
    u64 acc[12][2] = {};
    const ulonglong2* WT = (const ulonglong2*)g_gcnWT4;   // [f4*64+d] -> 2 pairs
#pragma unroll 4
    for (int f4 = 0; f4 < 48; f4++) {
        ulonglong2 wA = WT[f4*64 + d2];
        ulonglong2 wB = WT[f4*64 + d2 + 32];
        const float* hb = &Hc[nloc*2304 + f4*4];
#pragma unroll
        for (int t = 0; t < 12; t++) {
            ulonglong2 hp = *(const ulonglong2*)&hb[t*192];
            fma2(acc[t][0], hp.x, wA.x);
            fma2(acc[t][0], hp.y, wA.y);
            fma2(acc[t][1], hp.x, wB.x);
            fma2(acc[t][1], hp.y, wB.y);
        }
    }
    const int n = nBase + nloc;
#pragma unroll
    for (int dsel = 0; dsel < 2; dsel++) {
        int d = d2 + dsel*32;
        float bias = gcnB[d];
        float* op = out + ((size_t)(b*DD+d)*NN + n)*TT;
        float v[12];
#pragma unroll
        for (int t = 0; t < 12; t++) v[t] = lo2(acc[t][dsel]) + hi2(acc[t][dsel]) + bias;
#pragma unroll
        for (int q = 0; q < 3; q++)
            *(float4*)&op[q*4] = make_float4(v[q*4], v[q*4+1], v[q*4+2], v[q*4+3]);
    }
}

// ---------------- launcher ----------------
extern "C" void kernel_launch(void* const* d_in, const int* in_sizes, int n_in,
                              void* d_out, int out_size) {
    const float* X    = (const float*)d_in[0];
    const float* te   = (const float*)d_in[1];
    const float* adjW = (const float*)d_in[2];
    const float* adjB = (const float*)d_in[3];
    const float* tW1  = (const float*)d_in[4];
    const float* tW2  = (const float*)d_in[5];
    const float* a1   = (const float*)d_in[6];
    const float* a2   = (const float*)d_in[7];
    const float* b1   = (const float*)d_in[8];
    const float* b2   = (const float*)d_in[9];
    const float* gcnW = (const float*)d_in[10];
    const float* gcnB = (const float*)d_in[11];
    float* out = (float*)d_out;

    k_SB <<<(NN2 + 255)/256, 256>>>(a1, a2, b1, b2);
    k_Wp <<<(NN*DD*DD + 255)/256, 256>>>(tW1, tW2);
    k_gWT<<<(192*DD + 255)/256, 256>>>(gcnW);
    k_txp<<<dim3(NN, BB), 256>>>(X);

    k_adj<<<dim3(15, BT), 128>>>(te, adjW, adjB);

    // hop 1
    k_mm    <<<dim3(3, BT), 128>>>(0);
    k_nodemm<<<dim3(12, NN), 256>>>(0);
    // hop 2
    k_mm    <<<dim3(3, BT), 128>>>(1);
    k_nodemm<<<dim3(12, NN), 256>>>(1);

    k_out<<<dim3(75, BB), 128>>>(gcnB, out);
}

// round 5
// speedup vs baseline: 1.7140x; 1.0830x over previous
#include <cuda_runtime.h>
#include <math.h>

#define BB 32
#define NN 300
#define TT 12
#define DD 64
#define MM 16
#define BT (BB*TT)        // 384
#define ND (NN*DD)        // 19200
#define NN2 (NN*NN)       // 90000

// ---- scratch (device globals; no runtime allocation) ----
__device__ float g_S[NN2];             // alpha1@alpha2
__device__ float g_Bm[NN2];            // beta1@beta2
__device__ float g_W[NN*DD*DD];        // per-node weights [N,64,64]
__device__ float g_gcnWT4[192*DD];     // gcnW rearranged
__device__ float g_A[(size_t)BT*NN2];  // adjacency per (b,t)   ~138MB
__device__ float g_Xp[(size_t)BT*ND];  // X transposed [bt][n][d]
__device__ float g_H1[(size_t)BT*ND];
__device__ float g_H2[(size_t)BT*ND];
__device__ float g_Tmp[(size_t)BT*ND];

// ---- packed fp32x2 helpers (SASS FFMA2 path) ----
typedef unsigned long long u64;
__device__ __forceinline__ void fma2(u64 &d, u64 a, u64 b) {
    asm("fma.rn.f32x2 %0, %1, %2, %3;" : "=l"(d) : "l"(a), "l"(b), "l"(d));
}
__device__ __forceinline__ u64 rep2(float x) {
    u64 r; unsigned int u = __float_as_uint(x);
    asm("mov.b64 %0, {%1,%1};" : "=l"(r) : "r"(u));
    return r;
}
__device__ __forceinline__ float lo2(u64 v) { return __uint_as_float((unsigned)v); }
__device__ __forceinline__ float hi2(u64 v) { return __uint_as_float((unsigned)(v >> 32)); }

// gated residual: sigmoid(x)*tanh(x) == (1-e^-x)/(1+e^-2x); clamp keeps it finite
__device__ __forceinline__ float gated(float p) {
    float pc = fminf(fmaxf(p, -20.f), 20.f);
    float u = __expf(-pc);
    return __fdividef(1.f - u, 1.f + u*u);
}

// ---------------- tiny precompute kernels ----------------
__global__ void k_SB(const float* __restrict__ a1, const float* __restrict__ a2,
                     const float* __restrict__ b1, const float* __restrict__ b2) {
    int idx = blockIdx.x*256 + threadIdx.x;
    if (idx >= NN2) return;
    int i = idx / NN, k = idx % NN;
    float s = 0.f, bm = 0.f;
#pragma unroll
    for (int m = 0; m < MM; m++) {
        s  += a1[i*MM+m] * a2[m*NN+k];
        bm += b1[i*MM+m] * b2[m*NN+k];
    }
    g_S[idx] = s; g_Bm[idx] = bm;
}

__global__ void k_Wp(const float* __restrict__ w1, const float* __restrict__ w2) {
    int idx = blockIdx.x*256 + threadIdx.x;
    if (idx >= NN*DD*DD) return;
    int n = idx / (DD*DD), r = idx % (DD*DD);
    float s = 0.f;
#pragma unroll
    for (int m = 0; m < MM; m++) s += w1[n*MM+m] * w2[m*DD*DD+r];
    g_W[idx] = s;
}

__global__ void k_gWT(const float* __restrict__ gcnW) {
    int idx = blockIdx.x*256 + threadIdx.x;
    if (idx >= 192*DD) return;
    int i  = idx & 3;
    int d  = (idx >> 2) & 63;
    int f4 = idx >> 8;
    g_gcnWT4[idx] = gcnW[d*192 + f4*4 + i];
}

// transpose X[b,d,n,t] -> Xp[bt][n][d]
__global__ void k_txp(const float* __restrict__ X) {
    int n = blockIdx.x, b = blockIdx.y;
    __shared__ float tile[DD][13];
    int tid = threadIdx.x;
#pragma unroll
    for (int i = 0; i < 3; i++) {
        int lin = tid + i*256;
        if (lin < DD*TT) {
            int d = lin / TT, t = lin % TT;
            tile[d][t] = X[(((size_t)b*DD+d)*NN+n)*TT + t];
        }
    }
    __syncthreads();
#pragma unroll
    for (int i = 0; i < 3; i++) {
        int lin = tid + i*256;
        if (lin < DD*TT) {
            int t = lin >> 6, d = lin & 63;
            g_Xp[(size_t)(b*TT+t)*ND + n*DD + d] = tile[d][t];
        }
    }
}

// ---------------- adjacency: A = relu(S * sin(te@adjW^T + adjB) + Bm) ----------------
// tile 128 rows x 64 cols, 128 threads, 8x8 micro-tile via FFMA2
__global__ void __launch_bounds__(128) k_adj(const float* __restrict__ te,
                                             const float* __restrict__ adjW,
                                             const float* __restrict__ adjB) {
    const int bt = blockIdx.y;
    const int b = bt / TT, t = bt % TT;
    const int rt = blockIdx.x % 3;
    const int ct = blockIdx.x / 3;
    const int rowBase = rt*128, colBase = ct*64;
    __shared__ __align__(16) float As_t[32][132];
    __shared__ __align__(16) float Bs[32][68];
    const int tid = threadIdx.x;
    const int tx = tid & 7;
    const int ty = tid >> 3;
    u64 acc[4][8] = {};

    for (int k0 = 0; k0 < DD; k0 += 32) {
        {
            int row = rowBase + tid;
            const float* src = te + (((size_t)b*NN + row)*TT + t)*DD + k0;
#pragma unroll
            for (int c = 0; c < 8; c++) {
                float4 v = (row < NN) ? *(const float4*)(src + 4*c)
                                      : make_float4(0.f,0.f,0.f,0.f);
                As_t[4*c+0][tid] = v.x; As_t[4*c+1][tid] = v.y;
                As_t[4*c+2][tid] = v.z; As_t[4*c+3][tid] = v.w;
            }
        }
#pragma unroll
        for (int i = 0; i < 4; i++) {
            int lin = tid + i*128;
            int col = lin >> 3, kc = lin & 7;
            int gcol = colBase + col;
            float4 v = (gcol < NN) ? *(const float4*)(adjW + gcol*DD + k0 + kc*4)
                                   : make_float4(0.f,0.f,0.f,0.f);
            Bs[kc*4+0][col] = v.x; Bs[kc*4+1][col] = v.y;
            Bs[kc*4+2][col] = v.z; Bs[kc*4+3][col] = v.w;
        }
        __syncthreads();
#pragma unroll 8
        for (int kk = 0; kk < 32; kk++) {
            ulonglong2 ap0 = *(const ulonglong2*)&As_t[kk][ty*8];
            ulonglong2 ap1 = *(const ulonglong2*)&As_t[kk][ty*8+4];
            float4 b0 = *(const float4*)&Bs[kk][tx*8];
            float4 b1 = *(const float4*)&Bs[kk][tx*8+4];
            u64 ap[4] = {ap0.x, ap0.y, ap1.x, ap1.y};
            u64 br[8] = {rep2(b0.x),rep2(b0.y),rep2(b0.z),rep2(b0.w),
                         rep2(b1.x),rep2(b1.y),rep2(b1.z),rep2(b1.w)};
#pragma unroll
            for (int i = 0; i < 4; i++)
#pragma unroll
                for (int j = 0; j < 8; j++)
                    fma2(acc[i][j], ap[i], br[j]);
        }
        __syncthreads();
    }

    // epilogue: sin / scale / relu (MUFU.SIN)
    float* Aout = g_A + (size_t)bt*NN2;
    const int c0 = colBase + tx*8;
#pragma unroll
    for (int i = 0; i < 4; i++) {
        int r0 = rowBase + ty*8 + 2*i;
#pragma unroll
        for (int lane = 0; lane < 2; lane++) {
            int row = r0 + lane;
            if (row >= NN) continue;
#pragma unroll
            for (int j = 0; j < 8; j++) {
                int col = c0 + j;
                if (col >= NN) continue;
                float pre = lane ? hi2(acc[i][j]) : lo2(acc[i][j]);
                float v = __sinf(pre + adjB[col]);
                v = g_S[row*NN+col]*v + g_Bm[row*NN+col];
                Aout[(size_t)row*NN + col] = v > 0.f ? v : 0.f;
            }
        }
    }
}

// ---------------- Tmp = A @ Hb  (per bt: [300,300]@[300,64]) ----------------
__global__ void __launch_bounds__(128) k_mm(int hop) {
    const int bt = blockIdx.y;
    const int rowBase = blockIdx.x*128;
    const float* Hb = (hop == 0) ? g_Xp : g_H1;
    const float* Abt = g_A + (size_t)bt*NN2;
    const float* Hbt = Hb + (size_t)bt*ND;
    __shared__ __align__(16) float As_t[32][132];
    __shared__ __align__(16) float Bs[32][68];
    const int tid = threadIdx.x;
    const int tx = tid & 7;
    const int ty = tid >> 3;
    u64 acc[4][8] = {};

    for (int k0 = 0; k0 < 320; k0 += 32) {
        {
            int row = rowBase + tid;
            const float* src = Abt + (size_t)row*NN + k0;
#pragma unroll
            for (int c = 0; c < 8; c++) {
                float4 v;
                if (row < NN && (k0 + 4*c + 3) < NN) v = *(const float4*)(src + 4*c);
                else v = make_float4(0.f,0.f,0.f,0.f);
                As_t[4*c+0][tid] = v.x; As_t[4*c+1][tid] = v.y;
                As_t[4*c+2][tid] = v.z; As_t[4*c+3][tid] = v.w;
            }
        }
#pragma unroll
        for (int i = 0; i < 4; i++) {
            int lin = tid + i*128;
            int kk = lin >> 4, d4 = lin & 15;
            int k = k0 + kk;
            float4 v = (k < NN) ? *(const float4*)(Hbt + (size_t)k*DD + d4*4)
                                : make_float4(0.f,0.f,0.f,0.f);
            *(float4*)&Bs[kk][d4*4] = v;
        }
        __syncthreads();
#pragma unroll 8
        for (int kk = 0; kk < 32; kk++) {
            ulonglong2 ap0 = *(const ulonglong2*)&As_t[kk][ty*8];
            ulonglong2 ap1 = *(const ulonglong2*)&As_t[kk][ty*8+4];
            float4 b0 = *(const float4*)&Bs[kk][tx*8];
            float4 b1 = *(const float4*)&Bs[kk][tx*8+4];
            u64 ap[4] = {ap0.x, ap0.y, ap1.x, ap1.y};
            u64 br[8] = {rep2(b0.x),rep2(b0.y),rep2(b0.z),rep2(b0.w),
                         rep2(b1.x),rep2(b1.y),rep2(b1.z),rep2(b1.w)};
#pragma unroll
            for (int i = 0; i < 4; i++)
#pragma unroll
                for (int j = 0; j < 8; j++)
                    fma2(acc[i][j], ap[i], br[j]);
        }
        __syncthreads();
    }

    float* Tbt = g_Tmp + (size_t)bt*ND;
    const int c0 = tx*8;
#pragma unroll
    for (int i = 0; i < 4; i++) {
        int r0 = rowBase + ty*8 + 2*i;
        if (r0 < NN) {
            *(float4*)&Tbt[(size_t)r0*DD + c0] =
                make_float4(lo2(acc[i][0]), lo2(acc[i][1]), lo2(acc[i][2]), lo2(acc[i][3]));
            *(float4*)&Tbt[(size_t)r0*DD + c0 + 4] =
                make_float4(lo2(acc[i][4]), lo2(acc[i][5]), lo2(acc[i][6]), lo2(acc[i][7]));
        }
        if (r0 + 1 < NN) {
            *(float4*)&Tbt[(size_t)(r0+1)*DD + c0] =
                make_float4(hi2(acc[i][0]), hi2(acc[i][1]), hi2(acc[i][2]), hi2(acc[i][3]));
            *(float4*)&Tbt[(size_t)(r0+1)*DD + c0 + 4] =
                make_float4(hi2(acc[i][4]), hi2(acc[i][5]), hi2(acc[i][6]), hi2(acc[i][7]));
        }
    }
}

// ---------------- per-node matmul + gated residual (FFMA2) ----------------
// H[bt,n,:] = gated(Xp[bt,n,:] + Tmp[bt,n,:] @ W[n])
// grid (3, N): rows = 128 bt (all valid, 384=3*128), cols = 64 d, K = 64
__global__ void __launch_bounds__(128) k_nodemm(int hop) {
    const int n = blockIdx.y;
    const int rowBase = blockIdx.x*128;          // bt tile base
    float* Hout = (hop == 0) ? g_H1 : g_H2;
    const float* Wn = g_W + (size_t)n*DD*DD;
    __shared__ __align__(16) float As_t[32][132];   // [kk][btRow]
    __shared__ __align__(16) float Bs[32][68];      // [kk][d]
    const int tid = threadIdx.x;
    const int tx = tid & 7;
    const int ty = tid >> 3;
    u64 acc[4][8] = {};

    for (int k0 = 0; k0 < DD; k0 += 32) {
        {
            const float* src = g_Tmp + (size_t)(rowBase + tid)*ND + n*DD + k0;
#pragma unroll
            for (int c = 0; c < 8; c++) {
                float4 v = *(const float4*)(src + 4*c);
                As_t[4*c+0][tid] = v.x; As_t[4*c+1][tid] = v.y;
                As_t[4*c+2][tid] = v.z; As_t[4*c+3][tid] = v.w;
            }
        }
#pragma unroll
        for (int i = 0; i < 4; i++) {
            int lin = tid + i*128;
            int kk = lin >> 4, d4 = lin & 15;
            *(float4*)&Bs[kk][d4*4] = *(const float4*)(Wn + (size_t)(k0+kk)*DD + d4*4);
        }
        __syncthreads();
#pragma unroll 8
        for (int kk = 0; kk < 32; kk++) {
            ulonglong2 ap0 = *(const ulonglong2*)&As_t[kk][ty*8];
            ulonglong2 ap1 = *(const ulonglong2*)&As_t[kk][ty*8+4];
            float4 b0 = *(const float4*)&Bs[kk][tx*8];
            float4 b1 = *(const float4*)&Bs[kk][tx*8+4];
            u64 ap[4] = {ap0.x, ap0.y, ap1.x, ap1.y};
            u64 br[8] = {rep2(b0.x),rep2(b0.y),rep2(b0.z),rep2(b0.w),
                         rep2(b1.x),rep2(b1.y),rep2(b1.z),rep2(b1.w)};
#pragma unroll
            for (int i = 0; i < 4; i++)
#pragma unroll
                for (int j = 0; j < 8; j++)
                    fma2(acc[i][j], ap[i], br[j]);
        }
        __syncthreads();
    }

    // epilogue: gated residual, vectorized per row
    const int c0 = tx*8;
#pragma unroll
    for (int i = 0; i < 4; i++) {
        int r0 = rowBase + ty*8 + 2*i;
#pragma unroll
        for (int lane = 0; lane < 2; lane++) {
            int bt = r0 + lane;
            size_t base = (size_t)bt*ND + n*DD + c0;
            float4 x0 = *(const float4*)(g_Xp + base);
            float4 x1 = *(const float4*)(g_Xp + base + 4);
            float v[8];
#pragma unroll
            for (int j = 0; j < 8; j++)
                v[j] = lane ? hi2(acc[i][j]) : lo2(acc[i][j]);
            float4 o0, o1;
            o0.x = gated(x0.x + v[0]); o0.y = gated(x0.y + v[1]);
            o0.z = gated(x0.z + v[2]); o0.w = gated(x0.w + v[3]);
            o1.x = gated(x1.x + v[4]); o1.y = gated(x1.y + v[5]);
            o1.z = gated(x1.z + v[6]); o1.w = gated(x1.w + v[7]);
            *(float4*)(Hout + base) = o0;
            *(float4*)(Hout + base + 4) = o1;
        }
    }
}

// ---------------- output: [Xp|H1|H2] @ gcnW^T + gcnB -> [B,D,N,T] ----------------
__global__ void __launch_bounds__(128) k_out(const float* __restrict__ gcnB,
                                             float* __restrict__ out) {
    const int b = blockIdx.y;
    const int nBase = blockIdx.x*4;
    __shared__ __align__(16) float Hc[4*12*192];
    const int tid = threadIdx.x;
    float4* Hc4 = (float4*)Hc;
#pragma unroll
    for (int i = 0; i < 18; i++) {
        int lin4 = tid + i*128;
        int nl = lin4 / 576;
        int rem = lin4 - nl*576;
        int t = rem / 48;
        int f4 = rem - t*48;
        int seg = f4 >> 4, fd4 = f4 & 15;
        const float* src = (seg == 0) ? g_Xp : ((seg == 1) ? g_H1 : g_H2);
        Hc4[lin4] = *(const float4*)(src + (size_t)(b*TT+t)*ND + (nBase+nl)*DD + fd4*4);
    }
    __syncthreads();
    const int d2 = tid & 31, nloc = tid >> 5;
    u64 acc[12][2] = {};
    const ulonglong2* WT = (const ulonglong2*)g_gcnWT4;
#pragma unroll 4
    for (int f4 = 0; f4 < 48; f4++) {
        ulonglong2 wA = WT[f4*64 + d2];
        ulonglong2 wB = WT[f4*64 + d2 + 32];
        const float* hb = &Hc[nloc*2304 + f4*4];
#pragma unroll
        for (int t = 0; t < 12; t++) {
            ulonglong2 hp = *(const ulonglong2*)&hb[t*192];
            fma2(acc[t][0], hp.x, wA.x);
            fma2(acc[t][0], hp.y, wA.y);
            fma2(acc[t][1], hp.x, wB.x);
            fma2(acc[t][1], hp.y, wB.y);
        }
    }
    const int n = nBase + nloc;
#pragma unroll
    for (int dsel = 0; dsel < 2; dsel++) {
        int d = d2 + dsel*32;
        float bias = gcnB[d];
        float* op = out + ((size_t)(b*DD+d)*NN + n)*TT;
        float v[12];
#pragma unroll
        for (int t = 0; t < 12; t++) v[t] = lo2(acc[t][dsel]) + hi2(acc[t][dsel]) + bias;
#pragma unroll
        for (int q = 0; q < 3; q++)
            *(float4*)&op[q*4] = make_float4(v[q*4], v[q*4+1], v[q*4+2], v[q*4+3]);
    }
}

// ---------------- launcher ----------------
extern "C" void kernel_launch(void* const* d_in, const int* in_sizes, int n_in,
                              void* d_out, int out_size) {
    const float* X    = (const float*)d_in[0];
    const float* te   = (const float*)d_in[1];
    const float* adjW = (const float*)d_in[2];
    const float* adjB = (const float*)d_in[3];
    const float* tW1  = (const float*)d_in[4];
    const float* tW2  = (const float*)d_in[5];
    const float* a1   = (const float*)d_in[6];
    const float* a2   = (const float*)d_in[7];
    const float* b1   = (const float*)d_in[8];
    const float* b2   = (const float*)d_in[9];
    const float* gcnW = (const float*)d_in[10];
    const float* gcnB = (const float*)d_in[11];
    float* out = (float*)d_out;

    k_SB <<<(NN2 + 255)/256, 256>>>(a1, a2, b1, b2);
    k_Wp <<<(NN*DD*DD + 255)/256, 256>>>(tW1, tW2);
    k_gWT<<<(192*DD + 255)/256, 256>>>(gcnW);
    k_txp<<<dim3(NN, BB), 256>>>(X);

    k_adj<<<dim3(15, BT), 128>>>(te, adjW, adjB);

    // hop 1
    k_mm    <<<dim3(3, BT), 128>>>(0);
    k_nodemm<<<dim3(3, NN), 128>>>(0);
    // hop 2
    k_mm    <<<dim3(3, BT), 128>>>(1);
    k_nodemm<<<dim3(3, NN), 128>>>(1);

    k_out<<<dim3(75, BB), 128>>>(gcnB, out);
}